// round 1
// baseline (speedup 1.0000x reference)
#include <cuda_runtime.h>

#define B      4096
#define N_IN   512
#define H1     1536
#define H2     1536
#define N_OUT  512
#define NV_LD  3584   // N_IN + H1 + H2

// ---- scratch (static device globals; no allocation) ----
__device__ __align__(16) float g_W0[N_IN * H1];                  //  3.0 MB
__device__ __align__(16) float g_W1[(N_IN + H1) * H2];           // 12.6 MB
__device__ __align__(16) float g_W2[(N_IN + H1 + H2) * N_OUT];   //  7.3 MB
__device__ __align__(16) float g_nv[B * NV_LD];                  // 58.7 MB

// ---------------------------------------------------------------------------
// Zero all three dense weight matrices (float4 stores).
// ---------------------------------------------------------------------------
__global__ void zero_weights_kernel() {
    const int n0 = (N_IN * H1) / 4;
    const int n1 = ((N_IN + H1) * H2) / 4;
    const int n2 = ((N_IN + H1 + H2) * N_OUT) / 4;
    int i = blockIdx.x * blockDim.x + threadIdx.x;
    float4 z = make_float4(0.f, 0.f, 0.f, 0.f);
    if (i < n0) {
        reinterpret_cast<float4*>(g_W0)[i] = z;
    } else if (i < n0 + n1) {
        reinterpret_cast<float4*>(g_W1)[i - n0] = z;
    } else if (i < n0 + n1 + n2) {
        reinterpret_cast<float4*>(g_W2)[i - n0 - n1] = z;
    }
}

// ---------------------------------------------------------------------------
// Copy x [B, N_IN] into the first N_IN columns of g_nv (row stride NV_LD).
// ---------------------------------------------------------------------------
__global__ void copy_x_kernel(const float* __restrict__ x) {
    int i = blockIdx.x * blockDim.x + threadIdx.x;   // float4 index
    const int row4 = N_IN / 4;                       // 128 float4 per row
    if (i < B * row4) {
        int b = i / row4;
        int c = i - b * row4;
        reinterpret_cast<float4*>(g_nv + (size_t)b * NV_LD)[c] =
            reinterpret_cast<const float4*>(x)[i];
    }
}

// ---------------------------------------------------------------------------
// Densify one level's edges: W[src*N + dst] += w  (duplicates must sum).
// ---------------------------------------------------------------------------
__global__ void scatter_edges_kernel(const int* __restrict__ src,
                                     const int* __restrict__ dst,
                                     const float* __restrict__ w,
                                     int E, float* __restrict__ W, int N) {
    int i = blockIdx.x * blockDim.x + threadIdx.x;
    if (i < E) {
        atomicAdd(W + (size_t)src[i] * N + dst[i], w[i]);
    }
}

// ---------------------------------------------------------------------------
// C[m, n] = relu( sum_k A[m, k] * W[k, n] )
// A = g_nv (lda = NV_LD fixed). W row-major [K x N]. C with stride ldc.
// Tile: BM=128, BN=128, BK=16; 256 threads; 8x8 per thread.
// All problem dims divide tiles exactly -> no bounds checks.
// ---------------------------------------------------------------------------
__global__ void __launch_bounds__(256, 2)
gemm_relu_kernel(const float* __restrict__ A,
                 const float* __restrict__ W,
                 float* __restrict__ C, int ldc,
                 int N, int K) {
    const int BM = 128, BN = 128, BK = 16;
    __shared__ float As[BK][BM];   // transposed A tile
    __shared__ float Ws[BK][BN];

    const int bm  = blockIdx.x * BM;
    const int bn  = blockIdx.y * BN;
    const int tid = threadIdx.x;          // 0..255
    const int trow = tid >> 4;            // 0..15
    const int tcol = tid & 15;            // 0..15

    float acc[8][8];
#pragma unroll
    for (int i = 0; i < 8; i++)
#pragma unroll
        for (int j = 0; j < 8; j++) acc[i][j] = 0.f;

    for (int k0 = 0; k0 < K; k0 += BK) {
        // load A tile: 128 rows x 16 cols = 512 float4, 2 per thread
#pragma unroll
        for (int l = 0; l < 2; l++) {
            int t  = tid + l * 256;
            int r  = t >> 2;               // 0..127
            int c4 = t & 3;                // 0..3
            float4 v = *reinterpret_cast<const float4*>(
                A + (size_t)(bm + r) * NV_LD + k0 + c4 * 4);
            As[c4 * 4 + 0][r] = v.x;
            As[c4 * 4 + 1][r] = v.y;
            As[c4 * 4 + 2][r] = v.z;
            As[c4 * 4 + 3][r] = v.w;
        }
        // load W tile: 16 rows x 128 cols = 512 float4, 2 per thread
#pragma unroll
        for (int l = 0; l < 2; l++) {
            int t  = tid + l * 256;
            int r  = t >> 5;               // 0..15
            int c4 = t & 31;               // 0..31
            *reinterpret_cast<float4*>(&Ws[r][c4 * 4]) =
                *reinterpret_cast<const float4*>(W + (size_t)(k0 + r) * N + bn + c4 * 4);
        }
        __syncthreads();

#pragma unroll
        for (int k = 0; k < BK; k++) {
            float a[8], b[8];
#pragma unroll
            for (int i = 0; i < 4; i++) {
                float4 v = *reinterpret_cast<const float4*>(&As[k][trow * 8 + i * 4 - i * 4]);
                (void)v; // (kept simple below)
            }
            // simple scalar fills (compiler vectorizes LDS)
#pragma unroll
            for (int i = 0; i < 8; i++) a[i] = As[k][trow * 8 + i];
#pragma unroll
            for (int j = 0; j < 8; j++) b[j] = Ws[k][tcol * 8 + j];
#pragma unroll
            for (int i = 0; i < 8; i++)
#pragma unroll
                for (int j = 0; j < 8; j++)
                    acc[i][j] = fmaf(a[i], b[j], acc[i][j]);
        }
        __syncthreads();
    }

    // store with relu, float4
#pragma unroll
    for (int i = 0; i < 8; i++) {
        float* crow = C + (size_t)(bm + trow * 8 + i) * ldc + bn + tcol * 8;
#pragma unroll
        for (int j = 0; j < 8; j += 4) {
            float4 v;
            v.x = fmaxf(acc[i][j + 0], 0.f);
            v.y = fmaxf(acc[i][j + 1], 0.f);
            v.z = fmaxf(acc[i][j + 2], 0.f);
            v.w = fmaxf(acc[i][j + 3], 0.f);
            *reinterpret_cast<float4*>(crow + j) = v;
        }
    }
}

// ---------------------------------------------------------------------------
extern "C" void kernel_launch(void* const* d_in, const int* in_sizes, int n_in,
                              void* d_out, int out_size) {
    const float* x    = (const float*)d_in[0];
    const int*   src0 = (const int*)  d_in[1];
    const int*   dst0 = (const int*)  d_in[2];
    const float* w0   = (const float*)d_in[3];
    const int*   src1 = (const int*)  d_in[4];
    const int*   dst1 = (const int*)  d_in[5];
    const float* w1   = (const float*)d_in[6];
    const int*   src2 = (const int*)  d_in[7];
    const int*   dst2 = (const int*)  d_in[8];
    const float* w2   = (const float*)d_in[9];
    float* out = (float*)d_out;

    float* pW0; cudaGetSymbolAddress((void**)&pW0, g_W0);
    float* pW1; cudaGetSymbolAddress((void**)&pW1, g_W1);
    float* pW2; cudaGetSymbolAddress((void**)&pW2, g_W2);
    float* pnv; cudaGetSymbolAddress((void**)&pnv, g_nv);

    const int E1 = in_sizes[1];   // 49152
    const int E2 = in_sizes[4];   // 49152
    const int E3 = in_sizes[7];   // 16384

    // 1) zero dense weights
    {
        int total4 = (N_IN * H1 + (N_IN + H1) * H2 + (N_IN + H1 + H2) * N_OUT) / 4;
        zero_weights_kernel<<<(total4 + 255) / 256, 256>>>();
    }
    // 2) copy x into nv
    {
        int total4 = B * N_IN / 4;
        copy_x_kernel<<<(total4 + 255) / 256, 256>>>(x);
    }
    // 3) scatter edges into dense weights
    scatter_edges_kernel<<<(E1 + 255) / 256, 256>>>(src0, dst0, w0, E1, pW0, H1);
    scatter_edges_kernel<<<(E2 + 255) / 256, 256>>>(src1, dst1, w1, E2, pW1, H2);
    scatter_edges_kernel<<<(E3 + 255) / 256, 256>>>(src2, dst2, w2, E3, pW2, N_OUT);

    // 4) GEMM chain with fused relu
    dim3 blk(256);
    // level 1: h1 = relu(nv[:, :512] @ W0)   -> nv[:, 512:2048]
    gemm_relu_kernel<<<dim3(B / 128, H1 / 128), blk>>>(pnv, pW0, pnv + N_IN, NV_LD, H1, N_IN);
    // level 2: h2 = relu(nv[:, :2048] @ W1)  -> nv[:, 2048:3584]
    gemm_relu_kernel<<<dim3(B / 128, H2 / 128), blk>>>(pnv, pW1, pnv + N_IN + H1, NV_LD, H2, N_IN + H1);
    // level 3: out = relu(nv[:, :3584] @ W2) -> d_out
    gemm_relu_kernel<<<dim3(B / 128, N_OUT / 128), blk>>>(pnv, pW2, out, N_OUT, N_OUT, N_IN + H1 + H2);
}

// round 3
// speedup vs baseline: 2.4214x; 2.4214x over previous
#include <cuda_runtime.h>
#include <cuda_bf16.h>
#include <cstdint>

#define B_     4096
#define N_IN   512
#define H1     1536
#define H2     1536
#define N_OUT  512
#define NV_LD  3584
#define K1     512
#define K2     2048
#define K3     3584

// ---------------- static device scratch (no allocations) ----------------
__device__ __align__(16) float g_W0f[H1 * K1];
__device__ __align__(16) float g_W1f[H2 * K2];
__device__ __align__(16) float g_W2f[N_OUT * K3];
__device__ __align__(16) __nv_bfloat16 g_W0h[H1 * K1],    g_W0l[H1 * K1];
__device__ __align__(16) __nv_bfloat16 g_W1h[H2 * K2],    g_W1l[H2 * K2];
__device__ __align__(16) __nv_bfloat16 g_W2h[N_OUT * K3], g_W2l[N_OUT * K3];
__device__ __align__(16) __nv_bfloat16 g_nvh[B_ * NV_LD], g_nvl[B_ * NV_LD];

// ---------------- helpers ----------------
__device__ __forceinline__ uint32_t smem_u32(const void* p) {
    uint32_t a;
    asm("{ .reg .u64 t; cvta.to.shared.u64 t, %1; cvt.u32.u64 %0, t; }" : "=r"(a) : "l"(p));
    return a;
}
// 64B-row swizzle: rows of 64 bytes, 16B chunks; slot(bits6:4) unique across 8 rows
#define SWZ(off) ((off) ^ (((off) >> 3) & 0x30))

__device__ __forceinline__ void cp_async16(uint32_t dst, const void* src) {
    asm volatile("cp.async.cg.shared.global [%0], [%1], 16;"
                 :: "r"(dst), "l"(__cvta_generic_to_global(src)));
}
#define CP_COMMIT()  asm volatile("cp.async.commit_group;" ::: "memory")
#define CP_WAIT(n)   asm volatile("cp.async.wait_group %0;" :: "n"(n) : "memory")

__device__ __forceinline__ void ldmatrix_x4(uint32_t& r0, uint32_t& r1, uint32_t& r2, uint32_t& r3,
                                            uint32_t addr) {
    asm volatile("ldmatrix.sync.aligned.m8n8.x4.shared.b16 {%0,%1,%2,%3}, [%4];"
                 : "=r"(r0), "=r"(r1), "=r"(r2), "=r"(r3) : "r"(addr));
}
__device__ __forceinline__ void mma_bf16(float& c0, float& c1, float& c2, float& c3,
                                         uint32_t a0, uint32_t a1, uint32_t a2, uint32_t a3,
                                         uint32_t b0, uint32_t b1) {
    asm volatile(
        "mma.sync.aligned.m16n8k16.row.col.f32.bf16.bf16.f32 "
        "{%0,%1,%2,%3}, {%4,%5,%6,%7}, {%8,%9}, {%0,%1,%2,%3};"
        : "+f"(c0), "+f"(c1), "+f"(c2), "+f"(c3)
        : "r"(a0), "r"(a1), "r"(a2), "r"(a3), "r"(b0), "r"(b1));
}

__device__ __forceinline__ void split_bf16(float v, __nv_bfloat16& h, __nv_bfloat16& l) {
    h = __float2bfloat16(v);
    l = __float2bfloat16(v - __bfloat162float(h));
}

// ---------------- setup kernels ----------------
__global__ void zero_w_kernel() {
    const int n0 = (H1 * K1) / 4, n1 = (H2 * K2) / 4, n2 = (N_OUT * K3) / 4;
    int i = blockIdx.x * blockDim.x + threadIdx.x;
    float4 z = make_float4(0.f, 0.f, 0.f, 0.f);
    if (i < n0)                reinterpret_cast<float4*>(g_W0f)[i] = z;
    else if (i < n0 + n1)      reinterpret_cast<float4*>(g_W1f)[i - n0] = z;
    else if (i < n0 + n1 + n2) reinterpret_cast<float4*>(g_W2f)[i - n0 - n1] = z;
}

// transposed densify: W[dst, src] += w  (row-major [N, K])
__global__ void scatter_t_kernel(const int* __restrict__ src, const int* __restrict__ dst,
                                 const float* __restrict__ w, int E,
                                 float* __restrict__ W, int K) {
    int i = blockIdx.x * blockDim.x + threadIdx.x;
    if (i < E) atomicAdd(W + (size_t)dst[i] * K + src[i], w[i]);
}

__global__ void convert_w_kernel() {
    const int n0 = H1 * K1, n1 = H2 * K2, n2 = N_OUT * K3;
    int i = blockIdx.x * blockDim.x + threadIdx.x;
    float v; __nv_bfloat16 h, l;
    if (i < n0) {
        v = g_W0f[i]; split_bf16(v, h, l); g_W0h[i] = h; g_W0l[i] = l;
    } else if (i < n0 + n1) {
        int j = i - n0; v = g_W1f[j]; split_bf16(v, h, l); g_W1h[j] = h; g_W1l[j] = l;
    } else if (i < n0 + n1 + n2) {
        int j = i - n0 - n1; v = g_W2f[j]; split_bf16(v, h, l); g_W2h[j] = h; g_W2l[j] = l;
    }
}

__global__ void convert_x_kernel(const float* __restrict__ x) {
    int i = blockIdx.x * blockDim.x + threadIdx.x;
    if (i < B_ * N_IN) {
        int b = i / N_IN, c = i - b * N_IN;
        __nv_bfloat16 h, l;
        split_bf16(x[i], h, l);
        g_nvh[(size_t)b * NV_LD + c] = h;
        g_nvl[(size_t)b * NV_LD + c] = l;
    }
}

// ---------------- bf16x3-split HMMA GEMM ----------------
// C[128 x 128 per CTA] = relu(A @ B^T); A hi/lo [4096, K] stride NV_LD, B hi/lo [N, K].
// Accumulates Ah*Bh + Ah*Bl + Al*Bh in fp32 register accumulators.
// BK=32, 4-stage cp.async pipeline, 256 threads, warp tile 64x32.
__global__ void __launch_bounds__(256, 2)
gemm_hmma_kernel(const __nv_bfloat16* __restrict__ Ah, const __nv_bfloat16* __restrict__ Al,
                 const __nv_bfloat16* __restrict__ Bh, const __nv_bfloat16* __restrict__ Bl,
                 int K,
                 __nv_bfloat16* __restrict__ Chi, __nv_bfloat16* __restrict__ Clo,
                 float* __restrict__ Cf, int ldc) {
    constexpr int S = 4;               // pipeline stages
    constexpr int TILE = 128 * 64;     // bytes: 128 rows x 64B (32 bf16)
    constexpr int STAGE = 2 * TILE;    // A tile + B tile

    extern __shared__ char smem[];
    const uint32_t sA = smem_u32(smem);          // stage s: A at sA + s*STAGE, B at +TILE
    const int tid = threadIdx.x, wid = tid >> 5, lid = tid & 31;
    const int bm = blockIdx.x * 128, bn = blockIdx.y * 128;
    const int wm = (wid & 1) * 64, wn = (wid >> 1) * 32;
    const int CPS = K >> 5;            // 32-wide k chunks per split
    const int NC = 3 * CPS;

    float acc[4][4][4];
#pragma unroll
    for (int i = 0; i < 4; i++)
#pragma unroll
        for (int j = 0; j < 4; j++)
#pragma unroll
            for (int e = 0; e < 4; e++) acc[i][j][e] = 0.f;

    // per-chunk tile loader: 2 x 16B per thread per tile
    auto load_chunk = [&](int c, int s) {
        const int split = c / CPS;
        const int kc = (c - split * CPS) << 5;
        const __nv_bfloat16* Ap = (split == 2) ? Al : Ah;
        const __nv_bfloat16* Bp = (split == 1) ? Bl : Bh;
        const uint32_t base = sA + (uint32_t)s * STAGE;
#pragma unroll
        for (int l = 0; l < 2; l++) {
            int u = tid + l * 256;
            int r = u >> 2, c4 = u & 3;
            uint32_t off = (uint32_t)(r * 64 + c4 * 16);
            cp_async16(base + SWZ(off),
                       Ap + (size_t)(bm + r) * NV_LD + kc + c4 * 8);
            cp_async16(base + TILE + SWZ(off),
                       Bp + (size_t)(bn + r) * K + kc + c4 * 8);
        }
    };

    // prologue: stages 0..S-2
#pragma unroll
    for (int c = 0; c < S - 1; c++) {
        load_chunk(c, c);
        CP_COMMIT();
    }

    // ldmatrix lane addressing (stage-relative byte offsets, computed once)
    // A frag (mi, ks): rows wm+mi*16+(lid&15), k-half = ks*16 + 8*(lid>>4)
    const int a_row = wm + (lid & 15);
    const int a_kh0 = (lid >> 4) << 3;
    // B frag (nj, ks): rows wn+nj*16+(lid&7)+8*(lid>=16), k-half = ks*16 + (lid&8)
    const int b_row = wn + (lid & 7) + ((lid & 16) >> 1);
    const int b_kh0 = lid & 8;

    for (int c = 0; c < NC; c++) {
        CP_WAIT(2);
        __syncthreads();
        const int lc = c + S - 1;
        if (lc < NC) load_chunk(lc, lc & 3);
        CP_COMMIT();

        const uint32_t aBase = sA + (uint32_t)(c & 3) * STAGE;
        const uint32_t bBase = aBase + TILE;
#pragma unroll
        for (int ks = 0; ks < 2; ks++) {
            uint32_t a[4][4], b[4][2];
#pragma unroll
            for (int mi = 0; mi < 4; mi++) {
                uint32_t off = (uint32_t)((a_row + mi * 16) * 64 + (ks * 16 + a_kh0) * 2);
                ldmatrix_x4(a[mi][0], a[mi][1], a[mi][2], a[mi][3], aBase + SWZ(off));
            }
#pragma unroll
            for (int nj = 0; nj < 2; nj++) {
                uint32_t off = (uint32_t)((b_row + nj * 16) * 64 + (ks * 16 + b_kh0) * 2);
                uint32_t r0, r1, r2, r3;
                ldmatrix_x4(r0, r1, r2, r3, bBase + SWZ(off));
                b[nj * 2 + 0][0] = r0; b[nj * 2 + 0][1] = r1;
                b[nj * 2 + 1][0] = r2; b[nj * 2 + 1][1] = r3;
            }
#pragma unroll
            for (int mi = 0; mi < 4; mi++)
#pragma unroll
                for (int nj = 0; nj < 4; nj++)
                    mma_bf16(acc[mi][nj][0], acc[mi][nj][1], acc[mi][nj][2], acc[mi][nj][3],
                             a[mi][0], a[mi][1], a[mi][2], a[mi][3],
                             b[nj][0], b[nj][1]);
        }
    }

    // ---- epilogue: relu (+ bf16 hi/lo split for intermediate levels) ----
    const int er0 = bm + wm + (lid >> 2);
    const int ec  = bn + wn + (lid & 3) * 2;
#pragma unroll
    for (int mi = 0; mi < 4; mi++) {
#pragma unroll
        for (int nj = 0; nj < 4; nj++) {
            float v0 = fmaxf(acc[mi][nj][0], 0.f);
            float v1 = fmaxf(acc[mi][nj][1], 0.f);
            float v2 = fmaxf(acc[mi][nj][2], 0.f);
            float v3 = fmaxf(acc[mi][nj][3], 0.f);
            int r0 = er0 + mi * 16, r1 = r0 + 8;
            int cc = ec + nj * 8;
            if (Cf != nullptr) {
                *reinterpret_cast<float2*>(Cf + (size_t)r0 * ldc + cc) = make_float2(v0, v1);
                *reinterpret_cast<float2*>(Cf + (size_t)r1 * ldc + cc) = make_float2(v2, v3);
            } else {
                __nv_bfloat16 h0, l0, h1, l1, h2, l2, h3, l3;
                split_bf16(v0, h0, l0); split_bf16(v1, h1, l1);
                split_bf16(v2, h2, l2); split_bf16(v3, h3, l3);
                *reinterpret_cast<__nv_bfloat162*>(Chi + (size_t)r0 * ldc + cc) = __halves2bfloat162(h0, h1);
                *reinterpret_cast<__nv_bfloat162*>(Clo + (size_t)r0 * ldc + cc) = __halves2bfloat162(l0, l1);
                *reinterpret_cast<__nv_bfloat162*>(Chi + (size_t)r1 * ldc + cc) = __halves2bfloat162(h2, h3);
                *reinterpret_cast<__nv_bfloat162*>(Clo + (size_t)r1 * ldc + cc) = __halves2bfloat162(l2, l3);
            }
        }
    }
}

// ---------------- launch ----------------
extern "C" void kernel_launch(void* const* d_in, const int* in_sizes, int n_in,
                              void* d_out, int out_size) {
    const float* x    = (const float*)d_in[0];
    const int*   src0 = (const int*)  d_in[1];
    const int*   dst0 = (const int*)  d_in[2];
    const float* w0   = (const float*)d_in[3];
    const int*   src1 = (const int*)  d_in[4];
    const int*   dst1 = (const int*)  d_in[5];
    const float* w1   = (const float*)d_in[6];
    const int*   src2 = (const int*)  d_in[7];
    const int*   dst2 = (const int*)  d_in[8];
    const float* w2   = (const float*)d_in[9];
    float* out = (float*)d_out;

    float *pW0f, *pW1f, *pW2f;
    cudaGetSymbolAddress((void**)&pW0f, g_W0f);
    cudaGetSymbolAddress((void**)&pW1f, g_W1f);
    cudaGetSymbolAddress((void**)&pW2f, g_W2f);
    __nv_bfloat16 *pW0h, *pW0l, *pW1h, *pW1l, *pW2h, *pW2l, *pnvh, *pnvl;
    cudaGetSymbolAddress((void**)&pW0h, g_W0h);
    cudaGetSymbolAddress((void**)&pW0l, g_W0l);
    cudaGetSymbolAddress((void**)&pW1h, g_W1h);
    cudaGetSymbolAddress((void**)&pW1l, g_W1l);
    cudaGetSymbolAddress((void**)&pW2h, g_W2h);
    cudaGetSymbolAddress((void**)&pW2l, g_W2l);
    cudaGetSymbolAddress((void**)&pnvh, g_nvh);
    cudaGetSymbolAddress((void**)&pnvl, g_nvl);

    const int E1 = in_sizes[1], E2 = in_sizes[4], E3 = in_sizes[7];

    constexpr int SMEM = 4 * 2 * 128 * 64;   // 65536 bytes
    cudaFuncSetAttribute(gemm_hmma_kernel, cudaFuncAttributeMaxDynamicSharedMemorySize, SMEM);

    // setup: densify transposed weights, split to bf16 hi/lo
    {
        int total4 = (H1 * K1 + H2 * K2 + N_OUT * K3) / 4;
        zero_w_kernel<<<(total4 + 255) / 256, 256>>>();
    }
    scatter_t_kernel<<<(E1 + 255) / 256, 256>>>(src0, dst0, w0, E1, pW0f, K1);
    scatter_t_kernel<<<(E2 + 255) / 256, 256>>>(src1, dst1, w1, E2, pW1f, K2);
    scatter_t_kernel<<<(E3 + 255) / 256, 256>>>(src2, dst2, w2, E3, pW2f, K3);
    {
        int total = H1 * K1 + H2 * K2 + N_OUT * K3;
        convert_w_kernel<<<(total + 255) / 256, 256>>>();
    }
    convert_x_kernel<<<(B_ * N_IN + 255) / 256, 256>>>(x);

    // level 1: h1 = relu(nv[:, :512] @ W0^T) -> nv cols [512, 2048)
    gemm_hmma_kernel<<<dim3(B_ / 128, H1 / 128), 256, SMEM>>>(
        pnvh, pnvl, pW0h, pW0l, K1, pnvh + N_IN, pnvl + N_IN, nullptr, NV_LD);
    // level 2: h2 = relu(nv[:, :2048] @ W1^T) -> nv cols [2048, 3584)
    gemm_hmma_kernel<<<dim3(B_ / 128, H2 / 128), 256, SMEM>>>(
        pnvh, pnvl, pW1h, pW1l, K2, pnvh + N_IN + H1, pnvl + N_IN + H1, nullptr, NV_LD);
    // level 3: out = relu(nv @ W2^T) -> d_out fp32
    gemm_hmma_kernel<<<dim3(B_ / 128, N_OUT / 128), 256, SMEM>>>(
        pnvh, pnvl, pW2h, pW2l, K3, nullptr, nullptr, out, N_OUT);
}

// round 4
// speedup vs baseline: 10.1423x; 4.1886x over previous
#include <cuda_runtime.h>
#include <cstdint>

#define B_     4096
#define N_IN   512
#define H1     1536
#define H2     1536
#define N_OUT  512
#define NODES  3584          // N_IN + H1 + H2
#define CAP    128           // bucket capacity per dst node (Poisson(32) max ~66)

// ---------------- static device scratch (no allocations) ----------------
// Transposed node values: nvT[node][batch].  Rows 0-511 = x^T,
// rows 512-2047 = h1^T, rows 2048-3583 = h2^T.
__device__ __align__(16) float g_nvT[NODES * B_];        // 58.7 MB
__device__ __align__(16) float g_outT[N_OUT * B_];       //  8.4 MB
// Per-dst edge buckets. cnt index space: [0,H1) level1, [H1,H1+H2) level2,
// [H1+H2, H1+H2+N_OUT) level3.
__device__ int   g_cnt[NODES];
__device__ int   g_bsrc[NODES * CAP];
__device__ float g_bw[NODES * CAP];

// ---------------- setup kernels ----------------
__global__ void zero_cnt_kernel() {
    int i = blockIdx.x * blockDim.x + threadIdx.x;
    if (i < NODES) g_cnt[i] = 0;
}

__global__ void bucket_kernel(const int* __restrict__ src, const int* __restrict__ dst,
                              const float* __restrict__ w, int E, int cbase) {
    int i = blockIdx.x * blockDim.x + threadIdx.x;
    if (i < E) {
        int d = cbase + dst[i];
        int c = atomicAdd(&g_cnt[d], 1);
        if (c < CAP) {
            g_bsrc[d * CAP + c] = src[i];
            g_bw[d * CAP + c]   = w[i];
        }
    }
}

// x [B_, N_IN] row-major -> g_nvT rows [0, N_IN)
__global__ void transpose_in_kernel(const float* __restrict__ x) {
    __shared__ float tile[32][33];
    const int bx = blockIdx.x * 32;   // node dim
    const int by = blockIdx.y * 32;   // batch dim
    const int tx = threadIdx.x, ty = threadIdx.y;   // (32, 8)
#pragma unroll
    for (int i = 0; i < 32; i += 8)
        tile[ty + i][tx] = x[(size_t)(by + ty + i) * N_IN + bx + tx];
    __syncthreads();
#pragma unroll
    for (int i = 0; i < 32; i += 8)
        g_nvT[(size_t)(bx + ty + i) * B_ + by + tx] = tile[tx][ty + i];
}

// g_outT [N_OUT, B_] -> out [B_, N_OUT]
__global__ void transpose_out_kernel(float* __restrict__ out) {
    __shared__ float tile[32][33];
    const int bd = blockIdx.x * 32;   // node dim
    const int bb = blockIdx.y * 32;   // batch dim
    const int tx = threadIdx.x, ty = threadIdx.y;   // (32, 8)
#pragma unroll
    for (int i = 0; i < 32; i += 8)
        tile[ty + i][tx] = g_outT[(size_t)(bd + ty + i) * B_ + bb + tx];
    __syncthreads();
#pragma unroll
    for (int i = 0; i < 32; i += 8)
        out[(size_t)(bb + ty + i) * N_OUT + bd + tx] = tile[tx][ty + i];
}

// ---------------- sparse level kernel ----------------
// One CTA = one dst node x one 2048-wide batch segment.
// out_base points at row 0 of this level's output region (row stride B_).
// out[d, b] = relu( sum_e w_e * nvT[src_e, b] )
__global__ void __launch_bounds__(256, 8)
level_kernel(int cbase, float* __restrict__ out_base) {
    const int d   = blockIdx.x;
    const int seg = blockIdx.y;
    const int t   = threadIdx.x;

    int cnt = g_cnt[cbase + d];
    if (cnt > CAP) cnt = CAP;
    const int*   bs = g_bsrc + (size_t)(cbase + d) * CAP;
    const float* bw = g_bw   + (size_t)(cbase + d) * CAP;

    const int c0 = seg * 2048 + t * 4;   // this thread's first column
    const float* __restrict__ nvT = g_nvT;

    float4 a0 = make_float4(0.f, 0.f, 0.f, 0.f);
    float4 a1 = make_float4(0.f, 0.f, 0.f, 0.f);

    int e = 0;
    for (; e + 2 <= cnt; e += 2) {
        const int   s0 = bs[e],     s1 = bs[e + 1];
        const float w0 = bw[e],     w1 = bw[e + 1];
        const float4* r0 = reinterpret_cast<const float4*>(nvT + (size_t)s0 * B_ + c0);
        const float4* r1 = reinterpret_cast<const float4*>(nvT + (size_t)s1 * B_ + c0);
        float4 v00 = r0[0], v01 = r0[256];     // +1024 floats
        float4 v10 = r1[0], v11 = r1[256];
        a0.x = fmaf(w0, v00.x, a0.x); a0.y = fmaf(w0, v00.y, a0.y);
        a0.z = fmaf(w0, v00.z, a0.z); a0.w = fmaf(w0, v00.w, a0.w);
        a1.x = fmaf(w0, v01.x, a1.x); a1.y = fmaf(w0, v01.y, a1.y);
        a1.z = fmaf(w0, v01.z, a1.z); a1.w = fmaf(w0, v01.w, a1.w);
        a0.x = fmaf(w1, v10.x, a0.x); a0.y = fmaf(w1, v10.y, a0.y);
        a0.z = fmaf(w1, v10.z, a0.z); a0.w = fmaf(w1, v10.w, a0.w);
        a1.x = fmaf(w1, v11.x, a1.x); a1.y = fmaf(w1, v11.y, a1.y);
        a1.z = fmaf(w1, v11.z, a1.z); a1.w = fmaf(w1, v11.w, a1.w);
    }
    if (e < cnt) {
        const int   s0 = bs[e];
        const float w0 = bw[e];
        const float4* r0 = reinterpret_cast<const float4*>(nvT + (size_t)s0 * B_ + c0);
        float4 v00 = r0[0], v01 = r0[256];
        a0.x = fmaf(w0, v00.x, a0.x); a0.y = fmaf(w0, v00.y, a0.y);
        a0.z = fmaf(w0, v00.z, a0.z); a0.w = fmaf(w0, v00.w, a0.w);
        a1.x = fmaf(w0, v01.x, a1.x); a1.y = fmaf(w0, v01.y, a1.y);
        a1.z = fmaf(w0, v01.z, a1.z); a1.w = fmaf(w0, v01.w, a1.w);
    }

    // relu + store
    a0.x = fmaxf(a0.x, 0.f); a0.y = fmaxf(a0.y, 0.f);
    a0.z = fmaxf(a0.z, 0.f); a0.w = fmaxf(a0.w, 0.f);
    a1.x = fmaxf(a1.x, 0.f); a1.y = fmaxf(a1.y, 0.f);
    a1.z = fmaxf(a1.z, 0.f); a1.w = fmaxf(a1.w, 0.f);
    float4* orow = reinterpret_cast<float4*>(out_base + (size_t)d * B_ + c0);
    orow[0]   = a0;
    orow[256] = a1;
}

// ---------------- launch ----------------
extern "C" void kernel_launch(void* const* d_in, const int* in_sizes, int n_in,
                              void* d_out, int out_size) {
    const float* x    = (const float*)d_in[0];
    const int*   src0 = (const int*)  d_in[1];
    const int*   dst0 = (const int*)  d_in[2];
    const float* w0   = (const float*)d_in[3];
    const int*   src1 = (const int*)  d_in[4];
    const int*   dst1 = (const int*)  d_in[5];
    const float* w1   = (const float*)d_in[6];
    const int*   src2 = (const int*)  d_in[7];
    const int*   dst2 = (const int*)  d_in[8];
    const float* w2   = (const float*)d_in[9];
    float* out = (float*)d_out;

    float* pnvT;  cudaGetSymbolAddress((void**)&pnvT, g_nvT);
    float* poutT; cudaGetSymbolAddress((void**)&poutT, g_outT);

    const int E1 = in_sizes[1], E2 = in_sizes[4], E3 = in_sizes[7];

    // 1) build per-dst edge buckets
    zero_cnt_kernel<<<(NODES + 255) / 256, 256>>>();
    bucket_kernel<<<(E1 + 255) / 256, 256>>>(src0, dst0, w0, E1, 0);
    bucket_kernel<<<(E2 + 255) / 256, 256>>>(src1, dst1, w1, E2, H1);
    bucket_kernel<<<(E3 + 255) / 256, 256>>>(src2, dst2, w2, E3, H1 + H2);

    // 2) transpose x into nvT rows [0, N_IN)
    transpose_in_kernel<<<dim3(N_IN / 32, B_ / 32), dim3(32, 8)>>>(x);

    // 3) sparse levels (each: grid = (#dst nodes, 2 batch segments))
    level_kernel<<<dim3(H1, 2),    256>>>(0,        pnvT + (size_t)N_IN * B_);
    level_kernel<<<dim3(H2, 2),    256>>>(H1,       pnvT + (size_t)(N_IN + H1) * B_);
    level_kernel<<<dim3(N_OUT, 2), 256>>>(H1 + H2,  poutT);

    // 4) transpose result to [B, N_OUT]
    transpose_out_kernel<<<dim3(N_OUT / 32, B_ / 32), dim3(32, 8)>>>(out);
}

// round 5
// speedup vs baseline: 15.5901x; 1.5371x over previous
#include <cuda_runtime.h>
#include <cuda_fp16.h>
#include <cstdint>

#define B_     4096
#define N_IN   512
#define H1     1536
#define H2     1536
#define N_OUT  512
#define NODES  3584          // N_IN + H1 + H2
#define CAP    128           // bucket capacity per dst node (Poisson(32), max ~66)

// ---------------- static device scratch (no allocations) ----------------
// Transposed node values, fp16: nvTh[node][batch]. Rows 0-511 = x^T,
// rows 512-2047 = h1^T, rows 2048-3583 = h2^T.   29.4 MB -> L2-resident.
__device__ __align__(16) __half g_nvTh[NODES * B_];
__device__ __align__(16) float  g_outT[N_OUT * B_];       // 8.4 MB, fp32
__device__ int   g_cnt[NODES];
__device__ int   g_bsrc[NODES * CAP];
__device__ float g_bw[NODES * CAP];

// ---------------- setup: transpose x (fp32 -> fp16) + zero bucket counts ----
__global__ void transpose_in_kernel(const float* __restrict__ x) {
    // merged: first block also zeros g_cnt
    if (blockIdx.x == 0 && blockIdx.y == 0) {
        for (int i = threadIdx.y * 32 + threadIdx.x; i < NODES; i += 256)
            g_cnt[i] = 0;
    }
    __shared__ float tile[32][33];
    const int bx = blockIdx.x * 32;   // node dim
    const int by = blockIdx.y * 32;   // batch dim
    const int tx = threadIdx.x, ty = threadIdx.y;   // (32, 8)
#pragma unroll
    for (int i = 0; i < 32; i += 8)
        tile[ty + i][tx] = x[(size_t)(by + ty + i) * N_IN + bx + tx];
    __syncthreads();
#pragma unroll
    for (int i = 0; i < 32; i += 8)
        g_nvTh[(size_t)(bx + ty + i) * B_ + by + tx] = __float2half(tile[tx][ty + i]);
}

// ---------------- setup: build all three levels' buckets in one kernel ----
__global__ void bucket_all_kernel(const int* __restrict__ src0, const int* __restrict__ dst0,
                                  const float* __restrict__ w0, int E1,
                                  const int* __restrict__ src1, const int* __restrict__ dst1,
                                  const float* __restrict__ w1, int E2,
                                  const int* __restrict__ src2, const int* __restrict__ dst2,
                                  const float* __restrict__ w2, int E3) {
    int i = blockIdx.x * blockDim.x + threadIdx.x;
    int s, d; float wv;
    if (i < E1) {
        s = src0[i]; d = dst0[i]; wv = w0[i];
    } else if (i < E1 + E2) {
        int j = i - E1;
        s = src1[j]; d = H1 + 0; wv = w1[j];
        d = H1 + dst1[j]; s = src1[j];
    } else if (i < E1 + E2 + E3) {
        int j = i - E1 - E2;
        s = src2[j]; d = H1 + H2 + dst2[j]; wv = w2[j];
    } else {
        return;
    }
    int c = atomicAdd(&g_cnt[d], 1);
    if (c < CAP) {
        g_bsrc[d * CAP + c] = s;
        g_bw[d * CAP + c]   = wv;
    }
}

// ---------------- output transpose: g_outT [N_OUT, B_] -> out [B_, N_OUT] ----
__global__ void transpose_out_kernel(float* __restrict__ out) {
    __shared__ float tile[32][33];
    const int bd = blockIdx.x * 32;   // node dim
    const int bb = blockIdx.y * 32;   // batch dim
    const int tx = threadIdx.x, ty = threadIdx.y;   // (32, 8)
#pragma unroll
    for (int i = 0; i < 32; i += 8)
        tile[ty + i][tx] = g_outT[(size_t)(bd + ty + i) * B_ + bb + tx];
    __syncthreads();
#pragma unroll
    for (int i = 0; i < 32; i += 8)
        out[(size_t)(bb + ty + i) * N_OUT + bd + tx] = tile[tx][ty + i];
}

// ---------------- sparse level kernel ----------------
// One CTA = one dst node x one 2048-col batch segment; 256 thr x 8 cols.
// acc fp32; input fp16; output fp16 (intermediate) or fp32 (final).
__device__ __forceinline__ void fma8(float* a, float w, uint4 v) {
    float2 f;
    f = __half22float2(*reinterpret_cast<__half2*>(&v.x));
    a[0] = fmaf(w, f.x, a[0]); a[1] = fmaf(w, f.y, a[1]);
    f = __half22float2(*reinterpret_cast<__half2*>(&v.y));
    a[2] = fmaf(w, f.x, a[2]); a[3] = fmaf(w, f.y, a[3]);
    f = __half22float2(*reinterpret_cast<__half2*>(&v.z));
    a[4] = fmaf(w, f.x, a[4]); a[5] = fmaf(w, f.y, a[5]);
    f = __half22float2(*reinterpret_cast<__half2*>(&v.w));
    a[6] = fmaf(w, f.x, a[6]); a[7] = fmaf(w, f.y, a[7]);
}

template <bool F32OUT>
__global__ void __launch_bounds__(256, 8)
level_kernel(int cbase, __half* __restrict__ outh, float* __restrict__ outf) {
    const int d   = blockIdx.x;
    const int seg = blockIdx.y;
    const int t   = threadIdx.x;

    int cnt = g_cnt[cbase + d];
    if (cnt > CAP) cnt = CAP;
    const int*   bs = g_bsrc + (size_t)(cbase + d) * CAP;
    const float* bw = g_bw   + (size_t)(cbase + d) * CAP;

    const int c0 = seg * 2048 + t * 8;
    const __half* __restrict__ nvTh = g_nvTh;

    float a[8];
#pragma unroll
    for (int j = 0; j < 8; j++) a[j] = 0.f;

    int e = 0;
    for (; e + 2 <= cnt; e += 2) {
        const int   s0 = bs[e],  s1 = bs[e + 1];
        const float w0 = bw[e],  w1 = bw[e + 1];
        uint4 v0 = *reinterpret_cast<const uint4*>(nvTh + (size_t)s0 * B_ + c0);
        uint4 v1 = *reinterpret_cast<const uint4*>(nvTh + (size_t)s1 * B_ + c0);
        fma8(a, w0, v0);
        fma8(a, w1, v1);
    }
    if (e < cnt) {
        uint4 v0 = *reinterpret_cast<const uint4*>(nvTh + (size_t)bs[e] * B_ + c0);
        fma8(a, bw[e], v0);
    }

#pragma unroll
    for (int j = 0; j < 8; j++) a[j] = fmaxf(a[j], 0.f);

    if (F32OUT) {
        float* p = outf + (size_t)d * B_ + c0;
        *reinterpret_cast<float4*>(p)     = make_float4(a[0], a[1], a[2], a[3]);
        *reinterpret_cast<float4*>(p + 4) = make_float4(a[4], a[5], a[6], a[7]);
    } else {
        uint4 o;
        __half2 h;
        h = __floats2half2_rn(a[0], a[1]); o.x = *reinterpret_cast<uint32_t*>(&h);
        h = __floats2half2_rn(a[2], a[3]); o.y = *reinterpret_cast<uint32_t*>(&h);
        h = __floats2half2_rn(a[4], a[5]); o.z = *reinterpret_cast<uint32_t*>(&h);
        h = __floats2half2_rn(a[6], a[7]); o.w = *reinterpret_cast<uint32_t*>(&h);
        *reinterpret_cast<uint4*>(outh + (size_t)d * B_ + c0) = o;
    }
}

// ---------------- launch ----------------
extern "C" void kernel_launch(void* const* d_in, const int* in_sizes, int n_in,
                              void* d_out, int out_size) {
    const float* x    = (const float*)d_in[0];
    const int*   src0 = (const int*)  d_in[1];
    const int*   dst0 = (const int*)  d_in[2];
    const float* w0   = (const float*)d_in[3];
    const int*   src1 = (const int*)  d_in[4];
    const int*   dst1 = (const int*)  d_in[5];
    const float* w1   = (const float*)d_in[6];
    const int*   src2 = (const int*)  d_in[7];
    const int*   dst2 = (const int*)  d_in[8];
    const float* w2   = (const float*)d_in[9];
    float* out = (float*)d_out;

    __half* pnvTh; cudaGetSymbolAddress((void**)&pnvTh, g_nvTh);
    float*  poutT; cudaGetSymbolAddress((void**)&poutT, g_outT);

    const int E1 = in_sizes[1], E2 = in_sizes[4], E3 = in_sizes[7];

    // 1) transpose x -> fp16 nvT rows [0, N_IN)  (+ zero bucket counts)
    transpose_in_kernel<<<dim3(N_IN / 32, B_ / 32), dim3(32, 8)>>>(x);

    // 2) build per-dst edge buckets for all three levels
    {
        int Etot = E1 + E2 + E3;
        bucket_all_kernel<<<(Etot + 255) / 256, 256>>>(
            src0, dst0, w0, E1, src1, dst1, w1, E2, src2, dst2, w2, E3);
    }

    // 3) sparse levels
    level_kernel<false><<<dim3(H1, 2),    256>>>(0,       pnvTh + (size_t)N_IN * B_,        nullptr);
    level_kernel<false><<<dim3(H2, 2),    256>>>(H1,      pnvTh + (size_t)(N_IN + H1) * B_, nullptr);
    level_kernel<true ><<<dim3(N_OUT, 2), 256>>>(H1 + H2, nullptr,                          poutT);

    // 4) transpose result to [B, N_OUT]
    transpose_out_kernel<<<dim3(N_OUT / 32, B_ / 32), dim3(32, 8)>>>(out);
}

// round 6
// speedup vs baseline: 15.8866x; 1.0190x over previous
#include <cuda_runtime.h>
#include <cuda_fp16.h>
#include <cstdint>

#define B_     4096
#define N_IN   512
#define H1     1536
#define H2     1536
#define N_OUT  512
#define NODES  3584          // N_IN + H1 + H2
#define CAP    128           // bucket capacity per dst node (Poisson(32), max ~66)

typedef unsigned long long u64;

// ---------------- static device scratch (no allocations) ----------------
__device__ __align__(16) __half g_nvTh[NODES * B_];      // 29.4 MB, L2-resident
__device__ __align__(16) float  g_outT[N_OUT * B_];      //  8.4 MB
__device__ int  g_cnt[NODES];
__device__ __align__(16) int2 g_bpack[NODES * CAP];      // (src, w-bits) per edge

// ---------------- packed f32x2 helpers ----------------
__device__ __forceinline__ u64 pack2(float x, float y) {
    u64 r;
    asm("mov.b64 %0, {%1, %2};" : "=l"(r) : "f"(x), "f"(y));
    return r;
}
__device__ __forceinline__ float2 unpack2(u64 v) {
    float2 f;
    asm("mov.b64 {%0, %1}, %2;" : "=f"(f.x), "=f"(f.y) : "l"(v));
    return f;
}
__device__ __forceinline__ void ffma2(u64& acc, u64 a, u64 b) {
    asm("fma.rn.f32x2 %0, %1, %2, %0;" : "+l"(acc) : "l"(a), "l"(b));
}
__device__ __forceinline__ u64 cvt2(uint32_t h2) {
    float2 f = __half22float2(*reinterpret_cast<const __half2*>(&h2));
    return pack2(f.x, f.y);
}

// ---------------- setup: transpose x (fp32 -> fp16) + zero bucket counts ----
__global__ void transpose_in_kernel(const float* __restrict__ x) {
    if (blockIdx.x == 0 && blockIdx.y == 0) {
        for (int i = threadIdx.y * 32 + threadIdx.x; i < NODES; i += 256)
            g_cnt[i] = 0;
    }
    __shared__ float tile[32][33];
    const int bx = blockIdx.x * 32;   // node dim
    const int by = blockIdx.y * 32;   // batch dim
    const int tx = threadIdx.x, ty = threadIdx.y;   // (32, 8)
#pragma unroll
    for (int i = 0; i < 32; i += 8)
        tile[ty + i][tx] = x[(size_t)(by + ty + i) * N_IN + bx + tx];
    __syncthreads();
#pragma unroll
    for (int i = 0; i < 32; i += 8)
        g_nvTh[(size_t)(bx + ty + i) * B_ + by + tx] = __float2half(tile[tx][ty + i]);
}

// ---------------- setup: build all three levels' buckets ----------------
__global__ void bucket_all_kernel(const int* __restrict__ src0, const int* __restrict__ dst0,
                                  const float* __restrict__ w0, int E1,
                                  const int* __restrict__ src1, const int* __restrict__ dst1,
                                  const float* __restrict__ w1, int E2,
                                  const int* __restrict__ src2, const int* __restrict__ dst2,
                                  const float* __restrict__ w2, int E3) {
    int i = blockIdx.x * blockDim.x + threadIdx.x;
    int s, d; float wv;
    if (i < E1) {
        s = src0[i];            d = dst0[i];            wv = w0[i];
    } else if (i < E1 + E2) {
        int j = i - E1;
        s = src1[j];            d = H1 + dst1[j];       wv = w1[j];
    } else if (i < E1 + E2 + E3) {
        int j = i - E1 - E2;
        s = src2[j];            d = H1 + H2 + dst2[j];  wv = w2[j];
    } else {
        return;
    }
    int c = atomicAdd(&g_cnt[d], 1);
    if (c < CAP)
        g_bpack[(size_t)d * CAP + c] = make_int2(s, __float_as_int(wv));
}

// ---------------- output transpose: g_outT [N_OUT, B_] -> out [B_, N_OUT] ----
__global__ void transpose_out_kernel(float* __restrict__ out) {
    __shared__ float tile[32][33];
    const int bd = blockIdx.x * 32;
    const int bb = blockIdx.y * 32;
    const int tx = threadIdx.x, ty = threadIdx.y;
#pragma unroll
    for (int i = 0; i < 32; i += 8)
        tile[ty + i][tx] = g_outT[(size_t)(bd + ty + i) * B_ + bb + tx];
    __syncthreads();
#pragma unroll
    for (int i = 0; i < 32; i += 8)
        out[(size_t)(bb + ty + i) * N_OUT + bd + tx] = tile[tx][ty + i];
}

// ---------------- sparse level kernel ----------------
// One CTA = one dst node x one 2048-col batch segment; 256 thr x 8 cols.
// fp16 values, fp32 packed-pair accumulation via FFMA2.
__device__ __forceinline__ void edge_fma(u64& a0, u64& a1, u64& a2, u64& a3,
                                         float w, uint4 v) {
    const u64 W = pack2(w, w);
    ffma2(a0, W, cvt2(v.x));
    ffma2(a1, W, cvt2(v.y));
    ffma2(a2, W, cvt2(v.z));
    ffma2(a3, W, cvt2(v.w));
}

template <bool F32OUT>
__global__ void __launch_bounds__(256, 7)
level_kernel(int cbase, __half* __restrict__ outh, float* __restrict__ outf) {
    const int d   = blockIdx.x;
    const int seg = blockIdx.y;
    const int t   = threadIdx.x;

    int cnt = g_cnt[cbase + d];
    if (cnt > CAP) cnt = CAP;
    const int2* bp = g_bpack + (size_t)(cbase + d) * CAP;

    const int c0 = seg * 2048 + t * 8;
    const __half* __restrict__ nvTh = g_nvTh;

    u64 a0 = 0, a1 = 0, a2 = 0, a3 = 0;    // (0.f, 0.f) pairs

    int e = 0;
    for (; e + 2 <= cnt; e += 2) {
        int4 ep = *reinterpret_cast<const int4*>(bp + e);   // s0, w0, s1, w1
        uint4 v0 = *reinterpret_cast<const uint4*>(nvTh + (size_t)ep.x * B_ + c0);
        uint4 v1 = *reinterpret_cast<const uint4*>(nvTh + (size_t)ep.z * B_ + c0);
        edge_fma(a0, a1, a2, a3, __int_as_float(ep.y), v0);
        edge_fma(a0, a1, a2, a3, __int_as_float(ep.w), v1);
    }
    if (e < cnt) {
        int2 ep = bp[e];
        uint4 v0 = *reinterpret_cast<const uint4*>(nvTh + (size_t)ep.x * B_ + c0);
        edge_fma(a0, a1, a2, a3, __int_as_float(ep.y), v0);
    }

    float2 f0 = unpack2(a0), f1 = unpack2(a1), f2 = unpack2(a2), f3 = unpack2(a3);
    float r[8] = { f0.x, f0.y, f1.x, f1.y, f2.x, f2.y, f3.x, f3.y };
#pragma unroll
    for (int j = 0; j < 8; j++) r[j] = fmaxf(r[j], 0.f);

    if (F32OUT) {
        float* p = outf + (size_t)d * B_ + c0;
        *reinterpret_cast<float4*>(p)     = make_float4(r[0], r[1], r[2], r[3]);
        *reinterpret_cast<float4*>(p + 4) = make_float4(r[4], r[5], r[6], r[7]);
    } else {
        uint4 o;
        __half2 h;
        h = __floats2half2_rn(r[0], r[1]); o.x = *reinterpret_cast<uint32_t*>(&h);
        h = __floats2half2_rn(r[2], r[3]); o.y = *reinterpret_cast<uint32_t*>(&h);
        h = __floats2half2_rn(r[4], r[5]); o.z = *reinterpret_cast<uint32_t*>(&h);
        h = __floats2half2_rn(r[6], r[7]); o.w = *reinterpret_cast<uint32_t*>(&h);
        *reinterpret_cast<uint4*>(outh + (size_t)d * B_ + c0) = o;
    }
}

// ---------------- launch ----------------
extern "C" void kernel_launch(void* const* d_in, const int* in_sizes, int n_in,
                              void* d_out, int out_size) {
    const float* x    = (const float*)d_in[0];
    const int*   src0 = (const int*)  d_in[1];
    const int*   dst0 = (const int*)  d_in[2];
    const float* w0   = (const float*)d_in[3];
    const int*   src1 = (const int*)  d_in[4];
    const int*   dst1 = (const int*)  d_in[5];
    const float* w1   = (const float*)d_in[6];
    const int*   src2 = (const int*)  d_in[7];
    const int*   dst2 = (const int*)  d_in[8];
    const float* w2   = (const float*)d_in[9];
    float* out = (float*)d_out;

    __half* pnvTh; cudaGetSymbolAddress((void**)&pnvTh, g_nvTh);
    float*  poutT; cudaGetSymbolAddress((void**)&poutT, g_outT);

    const int E1 = in_sizes[1], E2 = in_sizes[4], E3 = in_sizes[7];

    // 1) transpose x -> fp16 nvT rows [0, N_IN)  (+ zero bucket counts)
    transpose_in_kernel<<<dim3(N_IN / 32, B_ / 32), dim3(32, 8)>>>(x);

    // 2) build per-dst packed edge buckets for all three levels
    {
        int Etot = E1 + E2 + E3;
        bucket_all_kernel<<<(Etot + 255) / 256, 256>>>(
            src0, dst0, w0, E1, src1, dst1, w1, E2, src2, dst2, w2, E3);
    }

    // 3) sparse levels
    level_kernel<false><<<dim3(H1, 2),    256>>>(0,       pnvTh + (size_t)N_IN * B_,        nullptr);
    level_kernel<false><<<dim3(H2, 2),    256>>>(H1,      pnvTh + (size_t)(N_IN + H1) * B_, nullptr);
    level_kernel<true ><<<dim3(N_OUT, 2), 256>>>(H1 + H2, nullptr,                          poutT);

    // 4) transpose result to [B, N_OUT]
    transpose_out_kernel<<<dim3(N_OUT / 32, B_ / 32), dim3(32, 8)>>>(out);
}

// round 7
// speedup vs baseline: 15.8928x; 1.0004x over previous
#include <cuda_runtime.h>
#include <cuda_fp16.h>
#include <cstdint>

#define B_     4096
#define N_IN   512
#define H1     1536
#define H2     1536
#define N_OUT  512
#define NODES  3584          // N_IN + H1 + H2
#define CAP    128           // bucket capacity per dst (Poisson(32), max ~66)
#define TBLOCKS 2048         // transpose blocks in fused setup kernel (16 x 128)

typedef unsigned long long u64;

// ---------------- static device scratch (no allocations) ----------------
__device__ __align__(16) __half g_nvTh[NODES * B_];      // 29.4 MB, L2-resident
__device__ __align__(16) float  g_outT[N_OUT * B_];      //  8.4 MB
__device__ int  g_cnt[NODES];       // zero at module load; re-zeroed each call by transpose_out
__device__ __align__(16) int2 g_bpack[NODES * CAP];      // (src, w-bits)

// ---------------- packed f32x2 helpers ----------------
__device__ __forceinline__ u64 pack2(float x, float y) {
    u64 r; asm("mov.b64 %0, {%1, %2};" : "=l"(r) : "f"(x), "f"(y)); return r;
}
__device__ __forceinline__ float2 unpack2(u64 v) {
    float2 f; asm("mov.b64 {%0, %1}, %2;" : "=f"(f.x), "=f"(f.y) : "l"(v)); return f;
}
__device__ __forceinline__ void ffma2(u64& acc, u64 a, u64 b) {
    asm("fma.rn.f32x2 %0, %1, %2, %0;" : "+l"(acc) : "l"(a), "l"(b));
}
__device__ __forceinline__ u64 cvt2(uint32_t h2) {
    float2 f = __half22float2(*reinterpret_cast<const __half2*>(&h2));
    return pack2(f.x, f.y);
}

// ---------------- fused setup: transpose x -> fp16 nvT  +  bucket build ----
// Blocks [0, TBLOCKS): 32x32 transpose tiles of x.
// Blocks [TBLOCKS, ...): edge bucketing, 4 edges per thread (int4 loads).
// g_cnt is guaranteed zero on entry (static init / previous call's epilogue).
__global__ void setup_kernel(const float* __restrict__ x,
                             const int* __restrict__ src0, const int* __restrict__ dst0,
                             const float* __restrict__ w0, int E1,
                             const int* __restrict__ src1, const int* __restrict__ dst1,
                             const float* __restrict__ w1, int E2,
                             const int* __restrict__ src2, const int* __restrict__ dst2,
                             const float* __restrict__ w2, int E3) {
    const int tid = threadIdx.x;
    if (blockIdx.x < TBLOCKS) {
        __shared__ float tile[32][33];
        const int bx = (blockIdx.x & 15) * 32;   // node dim (512/32 = 16)
        const int by = (blockIdx.x >> 4) * 32;   // batch dim
        const int tx = tid & 31, ty = tid >> 5;  // 32 x 8
#pragma unroll
        for (int i = 0; i < 32; i += 8)
            tile[ty + i][tx] = x[(size_t)(by + ty + i) * N_IN + bx + tx];
        __syncthreads();
#pragma unroll
        for (int i = 0; i < 32; i += 8)
            g_nvTh[(size_t)(bx + ty + i) * B_ + by + tx] = __float2half(tile[tx][ty + i]);
        return;
    }
    // ---- bucket part: 4 consecutive edges per thread ----
    int i0 = ((blockIdx.x - TBLOCKS) * 256 + tid) * 4;
    const int Etot = E1 + E2 + E3;
    if (i0 >= Etot) return;
    const int *sp, *dp; const float* wp; int dbase, j0;
    if (i0 < E1)           { sp = src0; dp = dst0; wp = w0; dbase = 0;       j0 = i0; }
    else if (i0 < E1 + E2) { sp = src1; dp = dst1; wp = w1; dbase = H1;      j0 = i0 - E1; }
    else                   { sp = src2; dp = dst2; wp = w2; dbase = H1 + H2; j0 = i0 - E1 - E2; }
    int4   s = *reinterpret_cast<const int4*>(sp + j0);
    int4   d = *reinterpret_cast<const int4*>(dp + j0);
    float4 w = *reinterpret_cast<const float4*>(wp + j0);
#pragma unroll
    for (int k = 0; k < 4; k++) {
        int sk = (&s.x)[k];
        int dk = dbase + (&d.x)[k];
        float wk = (&w.x)[k];
        int c = atomicAdd(&g_cnt[dk], 1);
        if (c < CAP)
            g_bpack[(size_t)dk * CAP + c] = make_int2(sk, __float_as_int(wk));
    }
}

// ---------------- output transpose + cnt reset for next call ----------------
__global__ void transpose_out_kernel(float* __restrict__ out) {
    if (blockIdx.x == 0 && blockIdx.y == 0) {
        for (int i = threadIdx.y * 32 + threadIdx.x; i < NODES; i += 256)
            g_cnt[i] = 0;
    }
    __shared__ float tile[32][33];
    const int bd = blockIdx.x * 32;
    const int bb = blockIdx.y * 32;
    const int tx = threadIdx.x, ty = threadIdx.y;
#pragma unroll
    for (int i = 0; i < 32; i += 8)
        tile[ty + i][tx] = g_outT[(size_t)(bd + ty + i) * B_ + bb + tx];
    __syncthreads();
#pragma unroll
    for (int i = 0; i < 32; i += 8)
        out[(size_t)(bb + ty + i) * N_OUT + bd + tx] = tile[tx][ty + i];
}

// ---------------- sparse level kernel ----------------
// One CTA per dst node, all 4096 batch cols. Thread t owns two dense 8-col
// strips: [t*8, t*8+8) and [2048 + t*8, ...). fp16 values, f32x2 accumulate.
__device__ __forceinline__ void strip_fma(u64* a, u64 W, uint4 v) {
    ffma2(a[0], W, cvt2(v.x));
    ffma2(a[1], W, cvt2(v.y));
    ffma2(a[2], W, cvt2(v.z));
    ffma2(a[3], W, cvt2(v.w));
}

template <bool F32OUT>
__global__ void __launch_bounds__(256)
level_kernel(int cbase, __half* __restrict__ outh, float* __restrict__ outf) {
    const int d = blockIdx.x;
    const int t = threadIdx.x;

    int cnt = g_cnt[cbase + d];
    if (cnt > CAP) cnt = CAP;
    const int2* bp = g_bpack + (size_t)(cbase + d) * CAP;

    const int c0 = t * 8;                 // strip A; strip B at c0 + 2048
    const __half* __restrict__ nvTh = g_nvTh;

    u64 aA[4] = {0, 0, 0, 0};
    u64 aB[4] = {0, 0, 0, 0};

    int e = 0;
    for (; e + 2 <= cnt; e += 2) {
        int4 ep = *reinterpret_cast<const int4*>(bp + e);   // s0, w0, s1, w1
        const __half* r0 = nvTh + (size_t)ep.x * B_ + c0;
        const __half* r1 = nvTh + (size_t)ep.z * B_ + c0;
        uint4 v0a = *reinterpret_cast<const uint4*>(r0);
        uint4 v0b = *reinterpret_cast<const uint4*>(r0 + 2048);
        uint4 v1a = *reinterpret_cast<const uint4*>(r1);
        uint4 v1b = *reinterpret_cast<const uint4*>(r1 + 2048);
        u64 W0 = pack2(__int_as_float(ep.y), __int_as_float(ep.y));
        u64 W1 = pack2(__int_as_float(ep.w), __int_as_float(ep.w));
        strip_fma(aA, W0, v0a);
        strip_fma(aB, W0, v0b);
        strip_fma(aA, W1, v1a);
        strip_fma(aB, W1, v1b);
    }
    if (e < cnt) {
        int2 ep = bp[e];
        const __half* r0 = nvTh + (size_t)ep.x * B_ + c0;
        uint4 v0a = *reinterpret_cast<const uint4*>(r0);
        uint4 v0b = *reinterpret_cast<const uint4*>(r0 + 2048);
        u64 W0 = pack2(__int_as_float(ep.y), __int_as_float(ep.y));
        strip_fma(aA, W0, v0a);
        strip_fma(aB, W0, v0b);
    }

    float rA[8], rB[8];
#pragma unroll
    for (int j = 0; j < 4; j++) {
        float2 f = unpack2(aA[j]); rA[2 * j] = fmaxf(f.x, 0.f); rA[2 * j + 1] = fmaxf(f.y, 0.f);
        f = unpack2(aB[j]);        rB[2 * j] = fmaxf(f.x, 0.f); rB[2 * j + 1] = fmaxf(f.y, 0.f);
    }

    if (F32OUT) {
        float* p = outf + (size_t)d * B_ + c0;
        *reinterpret_cast<float4*>(p)          = make_float4(rA[0], rA[1], rA[2], rA[3]);
        *reinterpret_cast<float4*>(p + 4)      = make_float4(rA[4], rA[5], rA[6], rA[7]);
        *reinterpret_cast<float4*>(p + 2048)   = make_float4(rB[0], rB[1], rB[2], rB[3]);
        *reinterpret_cast<float4*>(p + 2052)   = make_float4(rB[4], rB[5], rB[6], rB[7]);
    } else {
        __half* p = outh + (size_t)d * B_ + c0;
        uint4 o; __half2 h;
        h = __floats2half2_rn(rA[0], rA[1]); o.x = *reinterpret_cast<uint32_t*>(&h);
        h = __floats2half2_rn(rA[2], rA[3]); o.y = *reinterpret_cast<uint32_t*>(&h);
        h = __floats2half2_rn(rA[4], rA[5]); o.z = *reinterpret_cast<uint32_t*>(&h);
        h = __floats2half2_rn(rA[6], rA[7]); o.w = *reinterpret_cast<uint32_t*>(&h);
        *reinterpret_cast<uint4*>(p) = o;
        h = __floats2half2_rn(rB[0], rB[1]); o.x = *reinterpret_cast<uint32_t*>(&h);
        h = __floats2half2_rn(rB[2], rB[3]); o.y = *reinterpret_cast<uint32_t*>(&h);
        h = __floats2half2_rn(rB[4], rB[5]); o.z = *reinterpret_cast<uint32_t*>(&h);
        h = __floats2half2_rn(rB[6], rB[7]); o.w = *reinterpret_cast<uint32_t*>(&h);
        *reinterpret_cast<uint4*>(p + 2048) = o;
    }
}

// ---------------- launch ----------------
extern "C" void kernel_launch(void* const* d_in, const int* in_sizes, int n_in,
                              void* d_out, int out_size) {
    const float* x    = (const float*)d_in[0];
    const int*   src0 = (const int*)  d_in[1];
    const int*   dst0 = (const int*)  d_in[2];
    const float* w0   = (const float*)d_in[3];
    const int*   src1 = (const int*)  d_in[4];
    const int*   dst1 = (const int*)  d_in[5];
    const float* w1   = (const float*)d_in[6];
    const int*   src2 = (const int*)  d_in[7];
    const int*   dst2 = (const int*)  d_in[8];
    const float* w2   = (const float*)d_in[9];
    float* out = (float*)d_out;

    __half* pnvTh; cudaGetSymbolAddress((void**)&pnvTh, g_nvTh);
    float*  poutT; cudaGetSymbolAddress((void**)&poutT, g_outT);

    const int E1 = in_sizes[1], E2 = in_sizes[4], E3 = in_sizes[7];
    const int Etot = E1 + E2 + E3;

    // 1) fused setup: transpose x (fp32->fp16) + build edge buckets
    {
        int bucketBlocks = (Etot + 1023) / 1024;   // 4 edges/thread, 256 thr
        setup_kernel<<<TBLOCKS + bucketBlocks, 256>>>(
            x, src0, dst0, w0, E1, src1, dst1, w1, E2, src2, dst2, w2, E3);
    }

    // 2) sparse levels (one CTA per dst node)
    level_kernel<false><<<H1,    256>>>(0,       pnvTh + (size_t)N_IN * B_,        nullptr);
    level_kernel<false><<<H2,    256>>>(H1,      pnvTh + (size_t)(N_IN + H1) * B_, nullptr);
    level_kernel<true ><<<N_OUT, 256>>>(H1 + H2, nullptr,                          poutT);

    // 3) transpose result to [B, N_OUT] (+ reset g_cnt for the next call)
    transpose_out_kernel<<<dim3(N_OUT / 32, B_ / 32), dim3(32, 8)>>>(out);
}